// round 17
// baseline (speedup 1.0000x reference)
#include <cuda_runtime.h>
#include <cuda_fp16.h>
#include <cstdint>

// ---------------- problem constants ---------------------------------------
#define BATCH 8
#define AGENTS 6
#define IMGS 48
#define CH 256
#define HH 32
#define WW 32
#define HW 1024
#define COUT 768
#define NITER 3
#define PP 34            // padded H/W

// ---------------- device scratch (allocation is forbidden) ----------------
static __device__ __align__(16) __half g_P[(size_t)IMGS * PP * PP * CH];        // x, fp16 NHWC
static __device__ __align__(16) __half g_S[(size_t)BATCH * PP * PP * 2 * CH];   // [S_hi|S_lo]
static __device__ __align__(16) __half g_wmain[(size_t)9 * 1536 * CH];          // [W1' ; W_hh]
static __device__ __align__(16) __half g_ws[(size_t)9 * COUT * 2 * CH];         // [w2'|w2']
static __device__ __align__(16) float g_bias[1536];
static __device__ __align__(16) float g_g1[(size_t)IMGS * 1536 * HW];           // gi | gh
static __device__ __align__(16) float g_gs[(size_t)BATCH * COUT * HW];          // W2'*S

// ---------------- helpers ---------------------------------------------------
__device__ __forceinline__ uint32_t smem_u32(const void* p) {
    uint32_t a;
    asm("{ .reg .u64 t; cvta.to.shared.u64 t, %1; cvt.u32.u64 %0, t; }"
        : "=r"(a) : "l"(p));
    return a;
}
__device__ __forceinline__ void cp16(uint32_t smem, const void* g) {
    asm volatile("cp.async.cg.shared.global [%0], [%1], 16;"
                 :: "r"(smem), "l"(g));
}
#define CP_COMMIT() asm volatile("cp.async.commit_group;" ::: "memory")
template <int N>
__device__ __forceinline__ void cp_wait() {
    asm volatile("cp.async.wait_group %0;" :: "n"(N) : "memory");
}
__device__ __forceinline__ void ldsm4(uint32_t& r0, uint32_t& r1, uint32_t& r2,
                                      uint32_t& r3, uint32_t addr) {
    asm volatile("ldmatrix.sync.aligned.m8n8.x4.shared.b16 {%0,%1,%2,%3}, [%4];"
                 : "=r"(r0), "=r"(r1), "=r"(r2), "=r"(r3) : "r"(addr));
}
__device__ __forceinline__ void mma_fp16(float* d, const uint32_t* a,
                                         const uint32_t* b) {
    asm volatile(
        "mma.sync.aligned.m16n8k16.row.col.f32.f16.f16.f32 "
        "{%0,%1,%2,%3},{%4,%5,%6,%7},{%8,%9},{%0,%1,%2,%3};"
        : "+f"(d[0]), "+f"(d[1]), "+f"(d[2]), "+f"(d[3])
        : "r"(a[0]), "r"(a[1]), "r"(a[2]), "r"(a[3]), "r"(b[0]), "r"(b[1]));
}

// ---------------- prep: build W1'=W1-W2/5, W_hh, w2'=W2/5, bias ------------
// w_ih flat: [768][512][9]; w_hh flat: [768][256][9]
__global__ void wprep_kernel(const float* __restrict__ w_ih,
                             const float* __restrict__ w_hh,
                             const float* __restrict__ b_ih,
                             const float* __restrict__ b_hh) {
    int idx = blockIdx.x * blockDim.x + threadIdx.x;
    const int n1 = 9 * 1536 * CH;                   // == 9*768*512
    if (idx < n1) {
        // g_wmain [t][oc(1536)][ci(256)]
        int t = idx / (1536 * CH);
        int rem = idx - t * (1536 * CH);
        int oc = rem / CH;
        int ci = rem - oc * CH;
        float v;
        if (oc < COUT)
            v = w_ih[((size_t)oc * 512 + ci) * 9 + t] -
                w_ih[((size_t)oc * 512 + 256 + ci) * 9 + t] * 0.2f;
        else
            v = w_hh[((size_t)(oc - COUT) * CH + ci) * 9 + t];
        g_wmain[idx] = __float2half(v);
        // g_ws [t][oc(768)][ci2(512)], value = w_ih[oc][256 + (ci2&255)]/5
        int oc2 = rem / (2 * CH);
        int ci2 = rem - oc2 * (2 * CH);
        int ciL = ci2 & 255;
        g_ws[idx] = __float2half(
            w_ih[((size_t)oc2 * 512 + 256 + ciL) * 9 + t] * 0.2f);
    }
    if (idx < 1536)
        g_bias[idx] = (idx < COUT) ? b_ih[idx] : b_hh[idx - COUT];
}

// ---------------- zero padded borders (g_P and g_S) -------------------------
__global__ void zero_border_kernel() {
    int idx = blockIdx.x * blockDim.x + threadIdx.x;
    const int n1 = IMGS * PP * PP * 32;            // g_P: 32 groups of 8ch
    const int n2 = BATCH * PP * PP * 64;           // g_S: 64 groups of 8ch
    float4 z = make_float4(0.f, 0.f, 0.f, 0.f);
    if (idx < n1) {
        int g = idx & 31;
        int pix = (idx >> 5) % (PP * PP);
        int img = idx / (32 * PP * PP);
        int pp = pix / PP, qq = pix % PP;
        if (pp == 0 || pp == PP - 1 || qq == 0 || qq == PP - 1)
            *(float4*)&g_P[((size_t)(img * PP * PP) + pix) * CH + g * 8] = z;
    } else if (idx - n1 < n2) {
        int i2 = idx - n1;
        int g = i2 & 63;
        int pix = (i2 >> 6) % (PP * PP);
        int b = i2 / (64 * PP * PP);
        int pp = pix / PP, qq = pix % PP;
        if (pp == 0 || pp == PP - 1 || qq == 0 || qq == PP - 1)
            *(float4*)&g_S[((size_t)(b * PP * PP) + pix) * 2 * CH + g * 8] = z;
    }
}

// ---------------- build padded NHWC x (fp16) + S hi/lo from NCHW fp32 ------
__global__ void build_nhwc_kernel(const float* __restrict__ src) {
    __shared__ float s[AGENTS][32][33];
    const int tid = threadIdx.x;
    const int px0 = blockIdx.x * 32;
    const int c0 = blockIdx.y * 32;
    const int b = blockIdx.z;

#pragma unroll
    for (int a = 0; a < AGENTS; ++a) {
        for (int e = tid; e < 32 * 32; e += 256) {
            int i = e >> 5, j = e & 31;
            s[a][i][j] =
                src[((size_t)((b * AGENTS + a) * CH + c0 + i)) * HW + px0 + j];
        }
    }
    __syncthreads();

    for (int e = tid; e < 32 * 32; e += 256) {
        int i = e & 31;
        int j = e >> 5;
        int px = px0 + j;
        int py = (px >> 5) + 1, qx = (px & 31) + 1;
        float sum = 0.f;
#pragma unroll
        for (int a = 0; a < AGENTS; ++a) sum += s[a][i][j];
#pragma unroll
        for (int a = 0; a < AGENTS; ++a) {
            size_t base = ((size_t)((b * AGENTS + a) * PP + py) * PP + qx) * CH;
            g_P[base + c0 + i] = __float2half(s[a][i][j]);
        }
        size_t sbase = ((size_t)(b * PP + py) * PP + qx) * 2 * CH;
        __half sh = __float2half(sum);
        g_S[sbase + c0 + i] = sh;
        g_S[sbase + CH + c0 + i] = __float2half(sum - __half2float(sh));
    }
}

// ---------------- mma.sync conv body ----------------------------------------
// CTA: 128 oc x 128 px, 256 threads (8 warps as 4m x 2n).
// K=64 per stage; A/B tiles 128 rows x 128B, chunk phys = c ^ (row&7).
// 3-stage ring (dist 2, cp_wait<1>); copy issue interleaved into compute.
#define STAGEB 32768
#define SMEMB (3 * STAGEB)          // 98304

template <int CI, int OCT, int PCHV, bool BIAS>
__device__ __forceinline__ void conv_body(
    uint32_t sb, const __half* __restrict__ W, const __half* __restrict__ act,
    const float* __restrict__ bias, float* __restrict__ outb,
    int ocb, int img) {
    const int tid = threadIdx.x;
    const int lane = tid & 31;
    const int wid = tid >> 5;
    const int wm = wid >> 1;
    const int wn = wid & 1;
    const int gid = lane >> 2;
    const int tig = lane & 3;

    const int y0 = blockIdx.x * 4;

    constexpr int S = (CI / 64) * 9;   // 36 or 72 (divisible by 3)
    constexpr int ACI = OCT * CI;      // offA step per tap

    const int r0 = tid >> 3;
    const int cA = tid & 7;
    const uint32_t sw = (uint32_t)((cA ^ (r0 & 7)) << 4);
    const uint32_t dA = (uint32_t)r0 * 128 + sw;
    const uint32_t dB = 16384u + dA;
    const int aofA = (ocb * 128 + r0) * CI + cA * 8;
    const int bofB = ((img * PP + y0) * PP + r0) * PCHV + cA * 8;

    const int lr = lane & 15, hb = lane >> 4;
    const uint32_t aoff0 = (uint32_t)((wm * 32 + lr) * 128) +
                           (uint32_t)((hb ^ (lr & 7)) << 4);
    const uint32_t boff0 = 16384u + (uint32_t)((wn * 64 + lr) * 128) +
                           (uint32_t)((hb ^ (lr & 7)) << 4);

    int tap_n = 0, kx_n = 0, chunkb = 0, offA = 0, offB = 0;
    auto adv = [&]() {
        if (++tap_n == 9) {
            tap_n = 0; kx_n = 0; chunkb += 64; offA = chunkb; offB = chunkb;
        } else {
            offA += ACI;
            if (++kx_n == 3) { kx_n = 0; offB += (PP - 2) * PCHV; }
            else offB += PCHV;
        }
    };
    auto issue = [&](uint32_t bb) {
#pragma unroll
        for (int it = 0; it < 4; ++it) {
            cp16(bb + dA + it * 4096, W + aofA + it * 32 * CI + offA);
            cp16(bb + dB + it * 4096, act + bofB + it * PP * PCHV + offB);
        }
        CP_COMMIT();
        adv();
    };

    float d[2][8][4];
#pragma unroll
    for (int mi = 0; mi < 2; ++mi)
#pragma unroll
        for (int ni = 0; ni < 8; ++ni)
#pragma unroll
            for (int k = 0; k < 4; ++k) d[mi][ni][k] = 0.f;

    auto step = [&](uint32_t cbase, uint32_t ibase, bool doIssue) {
#pragma unroll
        for (int ks = 0; ks < 4; ++ks) {
            const uint32_t kxx = (uint32_t)ks << 5;
            uint32_t ah[2][4];
#pragma unroll
            for (int mi = 0; mi < 2; ++mi) {
                uint32_t aaddr = cbase + ((aoff0 + mi * 2048) ^ kxx);
                ldsm4(ah[mi][0], ah[mi][1], ah[mi][2], ah[mi][3], aaddr);
            }
            uint32_t bb[8][2];
#pragma unroll
            for (int nj = 0; nj < 4; ++nj) {
                uint32_t q0, q1, q2, q3;
                ldsm4(q0, q1, q2, q3, cbase + ((boff0 + nj * 2048) ^ kxx));
                bb[nj * 2][0] = q0; bb[nj * 2][1] = q2;
                bb[nj * 2 + 1][0] = q1; bb[nj * 2 + 1][1] = q3;
            }
            if (doIssue) {
                cp16(ibase + dA + ks * 4096, W + aofA + ks * 32 * CI + offA);
                cp16(ibase + dB + ks * 4096, act + bofB + ks * PP * PCHV + offB);
            }
#pragma unroll
            for (int mi = 0; mi < 2; ++mi)
#pragma unroll
                for (int ni = 0; ni < 8; ++ni) mma_fp16(d[mi][ni], ah[mi], bb[ni]);
        }
        if (doIssue) { CP_COMMIT(); adv(); }
    };

    const uint32_t b0 = sb, b1 = sb + STAGEB, b2 = sb + 2 * STAGEB;
    issue(b0);
    issue(b1);
    int s = 0;
    for (; s + 3 < S; s += 3) {
        cp_wait<1>(); __syncthreads(); step(b0, b2, true);
        cp_wait<1>(); __syncthreads(); step(b1, b0, true);
        cp_wait<1>(); __syncthreads(); step(b2, b1, true);
    }
    cp_wait<1>(); __syncthreads(); step(b0, b2, true);
    cp_wait<1>(); __syncthreads(); step(b1, 0, false);
    cp_wait<0>(); __syncthreads(); step(b2, 0, false);

    // ---- epilogue
#pragma unroll
    for (int mi = 0; mi < 2; ++mi) {
        int oc_lo = ocb * 128 + wm * 32 + mi * 16 + gid;
        int oc_hi = oc_lo + 8;
        float bz0 = BIAS ? bias[oc_lo] : 0.f;
        float bz1 = BIAS ? bias[oc_hi] : 0.f;
        float* p0 = outb + ((size_t)img * OCT + oc_lo) * HW;
        float* p1 = outb + ((size_t)img * OCT + oc_hi) * HW;
#pragma unroll
        for (int ni = 0; ni < 8; ++ni) {
            int pix = y0 * 32 + wn * 64 + ni * 8 + tig * 2;
            float2 v0 = make_float2(d[mi][ni][0] + bz0, d[mi][ni][1] + bz0);
            float2 v1 = make_float2(d[mi][ni][2] + bz1, d[mi][ni][3] + bz1);
            *(float2*)(p0 + pix) = v0;
            *(float2*)(p1 + pix) = v1;
        }
    }
}

// merged conv: y<12 -> main conv (1536 oc, x, CI=256) into g_g1
//              y>=12 -> S conv (768 oc, S hi/lo, CI=512) into g_gs (z<8 only)
__global__ void __launch_bounds__(256, 2)
conv_merged_kernel() {
    extern __shared__ char smc[];
    const uint32_t sb = smem_u32(smc);
    const int yq = blockIdx.y;
    if (yq < 12) {
        conv_body<CH, 1536, CH, true>(sb, g_wmain, g_P, g_bias, g_g1,
                                      yq, blockIdx.z);
    } else {
        if (blockIdx.z >= BATCH) return;
        conv_body<2 * CH, COUT, 2 * CH, false>(sb, g_ws, g_S, nullptr, g_gs,
                                               yq - 12, blockIdx.z);
    }
}

// ---------------- GRU elementwise ------------------------------------------
__device__ __forceinline__ float sigmoidf_(float x) { return 1.0f / (1.0f + expf(-x)); }
__device__ __forceinline__ float tanhf_(float x) {
    float e = expf(2.0f * x);
    return 1.0f - 2.0f / (e + 1.0f);
}

__global__ void gru_kernel(const float* __restrict__ hsrc, float* __restrict__ dst) {
    int idx = blockIdx.x * blockDim.x + threadIdx.x;   // 48*256*256
    int p4 = idx & 255;
    int c = (idx >> 8) & 255;
    int img = idx >> 16;
    if (img >= IMGS) return;

    const float4* g14 = (const float4*)g_g1;
    const float4* gs4 = (const float4*)g_gs;

    size_t gbase = (size_t)img * 1536 * 256;
    size_t sbase = (size_t)(img / AGENTS) * COUT * 256;
    float4 ir = g14[gbase + (size_t)c * 256 + p4];
    float4 ii = g14[gbase + (size_t)(CH + c) * 256 + p4];
    float4 in_ = g14[gbase + (size_t)(2 * CH + c) * 256 + p4];
    float4 hr = g14[gbase + (size_t)(3 * CH + c) * 256 + p4];
    float4 hi = g14[gbase + (size_t)(4 * CH + c) * 256 + p4];
    float4 hn = g14[gbase + (size_t)(5 * CH + c) * 256 + p4];
    float4 sr = gs4[sbase + (size_t)c * 256 + p4];
    float4 si = gs4[sbase + (size_t)(CH + c) * 256 + p4];
    float4 sn = gs4[sbase + (size_t)(2 * CH + c) * 256 + p4];
    float4 h = ((const float4*)hsrc)[(size_t)(img * CH + c) * 256 + p4];

    ir.x += sr.x; ir.y += sr.y; ir.z += sr.z; ir.w += sr.w;
    ii.x += si.x; ii.y += si.y; ii.z += si.z; ii.w += si.w;
    in_.x += sn.x; in_.y += sn.y; in_.z += sn.z; in_.w += sn.w;

    float4 o;
    {
        float r = sigmoidf_(ir.x + hr.x), z = sigmoidf_(ii.x + hi.x);
        float n = tanhf_(in_.x + r * hn.x);
        o.x = n + z * (h.x - n);
    }
    {
        float r = sigmoidf_(ir.y + hr.y), z = sigmoidf_(ii.y + hi.y);
        float n = tanhf_(in_.y + r * hn.y);
        o.y = n + z * (h.y - n);
    }
    {
        float r = sigmoidf_(ir.z + hr.z), z = sigmoidf_(ii.z + hi.z);
        float n = tanhf_(in_.z + r * hn.z);
        o.z = n + z * (h.z - n);
    }
    {
        float r = sigmoidf_(ir.w + hr.w), z = sigmoidf_(ii.w + hi.w);
        float n = tanhf_(in_.w + r * hn.w);
        o.w = n + z * (h.w - n);
    }
    ((float4*)dst)[(size_t)(img * CH + c) * 256 + p4] = o;
}

// ---------------- launch ----------------------------------------------------
extern "C" void kernel_launch(void* const* d_in, const int* in_sizes, int n_in,
                              void* d_out, int out_size) {
    const float* x = (const float*)d_in[0];
    const float* w_ih = (const float*)d_in[1];
    const float* w_hh = (const float*)d_in[2];
    const float* b_ih = (const float*)d_in[3];
    const float* b_hh = (const float*)d_in[4];
    float* out = (float*)d_out;

    cudaFuncSetAttribute(conv_merged_kernel,
                         cudaFuncAttributeMaxDynamicSharedMemorySize, SMEMB);

    {
        int n = 9 * 1536 * CH;                       // 3,538,944 (covers g_ws too)
        wprep_kernel<<<(n + 255) / 256, 256>>>(w_ih, w_hh, b_ih, b_hh);
    }
    {
        int n = IMGS * PP * PP * 32 + BATCH * PP * PP * 64;
        zero_border_kernel<<<(n + 255) / 256, 256>>>();
    }

    dim3 bgrid(32, 8, BATCH);                  // px-tiles, c-tiles, b
    dim3 cgrid(8, 18, IMGS);                   // px-tiles, 12 main + 6 S, imgs
    const int gru_blocks = (IMGS * CH * 256 + 255) / 256;

    for (int it = 0; it < NITER; ++it) {
        const float* src = (it == 0) ? x : out;
        build_nhwc_kernel<<<bgrid, 256>>>(src);
        conv_merged_kernel<<<cgrid, 256, SMEMB>>>();
        gru_kernel<<<gru_blocks, 256>>>(src, out);
    }
}